// round 5
// baseline (speedup 1.0000x reference)
#include <cuda_runtime.h>
#include <cuda_bf16.h>

#define GSZ   32
#define NCTRL 68
#define MLS_EPS 1e-8f

typedef unsigned long long u64;

__device__ __forceinline__ u64 f2pack(float lo, float hi) {
    u64 r; asm("mov.b64 %0,{%1,%2};" : "=l"(r) : "f"(lo), "f"(hi)); return r;
}
__device__ __forceinline__ void f2unpack(u64 v, float& lo, float& hi) {
    asm("mov.b64 {%0,%1},%2;" : "=f"(lo), "=f"(hi) : "l"(v));
}
__device__ __forceinline__ float frcp(float x) {
    float r; asm("rcp.approx.f32 %0,%1;" : "=f"(r) : "f"(x)); return r;
}

// Entire per-control update in ONE asm block: all temporaries (dx, dy, w,
// wdx, wdy) are block-internal virtual registers, so the only register-pair
// webs crossing an asm boundary are the 12 in-place accumulators and the two
// LDS.128-loaded control words. This removes the pair-alignment marshaling
// MOVs that separate per-op asm blocks forced ptxas to insert.
__device__ __forceinline__ void mls_body(
    u64& sw, u64& Sx, u64& Sy, u64& Sxx, u64& Sxy, u64& Syy,
    u64& Sqx, u64& Sqy, u64& S1, u64& S2, u64& S3, u64& S4,
    u64 kx2, u64 ky2, u64 qx2, u64 qy2,
    u64 nvx2, u64 nvy2, u64 eps2)
{
    asm("{\n\t"
        ".reg .b64 dx, dy, w, wdx, wdy;\n\t"
        ".reg .f32 lo, hi;\n\t"
        "add.rn.f32x2 dx, %12, %16;\n\t"
        "add.rn.f32x2 dy, %13, %17;\n\t"
        "fma.rn.f32x2 w, dy, dy, %18;\n\t"
        "fma.rn.f32x2 w, dx, dx, w;\n\t"
        "mov.b64 {lo, hi}, w;\n\t"
        "rcp.approx.f32 lo, lo;\n\t"
        "rcp.approx.f32 hi, hi;\n\t"
        "mov.b64 w, {lo, hi};\n\t"
        "mul.rn.f32x2 wdx, w, dx;\n\t"
        "mul.rn.f32x2 wdy, w, dy;\n\t"
        "add.rn.f32x2 %0, %0, w;\n\t"
        "add.rn.f32x2 %1, %1, wdx;\n\t"
        "add.rn.f32x2 %2, %2, wdy;\n\t"
        "fma.rn.f32x2 %3, wdx, dx, %3;\n\t"
        "fma.rn.f32x2 %4, wdx, dy, %4;\n\t"
        "fma.rn.f32x2 %5, wdy, dy, %5;\n\t"
        "fma.rn.f32x2 %6, w, %14, %6;\n\t"
        "fma.rn.f32x2 %7, w, %15, %7;\n\t"
        "fma.rn.f32x2 %8, wdx, %14, %8;\n\t"
        "fma.rn.f32x2 %9, wdy, %14, %9;\n\t"
        "fma.rn.f32x2 %10, wdx, %15, %10;\n\t"
        "fma.rn.f32x2 %11, wdy, %15, %11;\n\t"
        "}"
        : "+l"(sw), "+l"(Sx), "+l"(Sy), "+l"(Sxx), "+l"(Sxy), "+l"(Syy),
          "+l"(Sqx), "+l"(Sqy), "+l"(S1), "+l"(S2), "+l"(S3), "+l"(S4)
        : "l"(kx2), "l"(ky2), "l"(qx2), "l"(qy2),
          "l"(nvx2), "l"(nvy2), "l"(eps2));
}

// Scalar epilogue: closed-form 2x2 solve from raw weighted moments.
//  m = Sigma w~ (pf - v)  ->  p* = v + m, u = v - p* = -m
__device__ __forceinline__ void mls_finish(
    float sw, float sx, float sy,
    float sxx, float sxy, float syy,
    float sqx, float sqy,
    float sdxqx, float sdyqx, float sdxqy, float sdyqy,
    float* __restrict__ ob, int pix)
{
    const float isw = frcp(sw);
    const float mx  = sx * isw,  my  = sy * isw;
    const float a11 = fmaf(sxx, isw, -(mx * mx));
    const float a12 = fmaf(sxy, isw, -(mx * my));
    const float a22 = fmaf(syy, isw, -(my * my));
    const float qsx = sqx * isw, qsy = sqy * isw;
    const float bxx = fmaf(sdxqx, isw, -(mx * qsx));
    const float bxy = fmaf(sdyqx, isw, -(my * qsx));
    const float byx = fmaf(sdxqy, isw, -(mx * qsy));
    const float byy = fmaf(sdyqy, isw, -(my * qsy));

    const float det  = fmaf(a11, a22, -(a12 * a12));
    const float idet = frcp(det);
    const float ux = -mx, uy = -my;
    const float rx = (ux * a22 - uy * a12) * idet;
    const float ry = (uy * a11 - ux * a12) * idet;

    float tx = fmaf(rx, bxx, fmaf(ry, bxy, qsx));
    float ty = fmaf(rx, byx, fmaf(ry, byy, qsy));

    // out-of-range pixels are ZEROED (not clipped)
    if (!(tx >= 0.f) || tx > (float)(GSZ - 1)) tx = 0.f;
    if (!(ty >= 0.f) || ty > (float)(GSZ - 1)) ty = 0.f;

    ob[pix]             = tx;   // channel 0 (x)
    ob[GSZ * GSZ + pix] = ty;   // channel 1 (y)
}

// 128 threads per CTA, each handles 2 pixels (pix, pix+128): same column,
// rows 4 apart. grid = (4, B): blockIdx.x selects an 8-row band.
__global__ __launch_bounds__(128)
void mls_warp_kernel(const float* __restrict__ sp,
                     const float* __restrict__ dp,
                     float* __restrict__ out)
{
    // Per control: 4 pre-duplicated f32x2 words: (kx,kx)(ky,ky)(qx,qx)(qy,qy)
    __shared__ __align__(16) u64 cs[NCTRL * 4];

    const int b    = blockIdx.y;
    const int band = blockIdx.x;     // 8-row band of the 32x32 grid
    const int tid  = threadIdx.x;

    if (tid < NCTRL) {
        const float* spb = sp + (size_t)b * (NCTRL * 2) + tid * 2;
        const float* dpb = dp + (size_t)b * (NCTRL * 2) + tid * 2;
        // coord swap + int16 truncation, exactly as the reference
        float kx = (float)(short)dpb[1];
        float ky = (float)(short)dpb[0];
        float qx = (float)(short)spb[1];
        float qy = (float)(short)spb[0];
        cs[tid * 4 + 0] = f2pack(kx, kx);
        cs[tid * 4 + 1] = f2pack(ky, ky);
        cs[tid * 4 + 2] = f2pack(qx, qx);
        cs[tid * 4 + 3] = f2pack(qy, qy);
    }
    __syncthreads();

    const int pixA = band * 256 + tid;         // pixB = pixA + 128
    const float vx  = (float)(tid & 31);
    const float vyA = (float)(band * 8 + (tid >> 5));
    const float vyB = vyA + 4.0f;

    const u64 nvx2 = f2pack(-vx, -vx);
    const u64 nvy2 = f2pack(-vyA, -vyB);
    const u64 eps2 = f2pack(MLS_EPS, MLS_EPS);

    u64 sw = 0, Sx = 0, Sy = 0;
    u64 Sxx = 0, Sxy = 0, Syy = 0;
    u64 Sqx = 0, Sqy = 0;
    u64 Sdxqx = 0, Sdyqx = 0, Sdxqy = 0, Sdyqy = 0;

    const ulonglong2* csv = (const ulonglong2*)cs;
#pragma unroll 4
    for (int c = 0; c < NCTRL; ++c) {
        ulonglong2 u0 = csv[c * 2 + 0];        // (kx2, ky2)
        ulonglong2 u1 = csv[c * 2 + 1];        // (qx2, qy2)
        mls_body(sw, Sx, Sy, Sxx, Sxy, Syy, Sqx, Sqy,
                 Sdxqx, Sdyqx, Sdxqy, Sdyqy,
                 u0.x, u0.y, u1.x, u1.y, nvx2, nvy2, eps2);
    }

    float* ob = out + (size_t)b * (2 * GSZ * GSZ);

    float swl, swh, sxl, sxh, syl, syh;
    float sxxl, sxxh, sxyl, sxyh, syyl, syyh;
    float sqxl, sqxh, sqyl, sqyh;
    float s1l, s1h, s2l, s2h, s3l, s3h, s4l, s4h;
    f2unpack(sw, swl, swh);    f2unpack(Sx, sxl, sxh);    f2unpack(Sy, syl, syh);
    f2unpack(Sxx, sxxl, sxxh); f2unpack(Sxy, sxyl, sxyh); f2unpack(Syy, syyl, syyh);
    f2unpack(Sqx, sqxl, sqxh); f2unpack(Sqy, sqyl, sqyh);
    f2unpack(Sdxqx, s1l, s1h); f2unpack(Sdyqx, s2l, s2h);
    f2unpack(Sdxqy, s3l, s3h); f2unpack(Sdyqy, s4l, s4h);

    mls_finish(swl, sxl, syl, sxxl, sxyl, syyl, sqxl, sqyl, s1l, s2l, s3l, s4l, ob, pixA);
    mls_finish(swh, sxh, syh, sxxh, sxyh, syyh, sqxh, sqyh, s1h, s2h, s3h, s4h, ob, pixA + 128);
}

extern "C" void kernel_launch(void* const* d_in, const int* in_sizes, int n_in,
                              void* d_out, int out_size)
{
    const float* sp = (const float*)d_in[0];   // (B, 68, 2)
    const float* dp = (const float*)d_in[1];   // (B, 68, 2)
    float* out = (float*)d_out;                // (B, 2, 32, 32)

    int B = in_sizes[0] / (NCTRL * 2);         // 512 for this problem
    dim3 grid(4, B);
    mls_warp_kernel<<<grid, 128>>>(sp, dp, out);
}

// round 9
// speedup vs baseline: 1.0299x; 1.0299x over previous
#include <cuda_runtime.h>
#include <cuda_bf16.h>

#define GSZ   32
#define NCTRL 68
#define MLS_EPS 1e-8f

typedef unsigned long long u64;

__device__ __forceinline__ u64 f2pack(float lo, float hi) {
    u64 r; asm("mov.b64 %0,{%1,%2};" : "=l"(r) : "f"(lo), "f"(hi)); return r;
}
__device__ __forceinline__ void f2unpack(u64 v, float& lo, float& hi) {
    asm("mov.b64 {%0,%1},%2;" : "=f"(lo), "=f"(hi) : "l"(v));
}
__device__ __forceinline__ float frcp(float x) {
    float r; asm("rcp.approx.f32 %0,%1;" : "=f"(r) : "f"(x)); return r;
}

// Entire per-control update in ONE asm block, INCLUDING the shared-memory
// loads of the control words. The only operands crossing the asm boundary are
// one 32-bit shared address, three loop-invariant constants, and the 12
// in-place accumulators -- so there are no per-iteration register-pair webs
// for ptxas to satisfy with marshaling MOVs.
__device__ __forceinline__ void mls_body(
    u64& sw, u64& Sx, u64& Sy, u64& Sxx, u64& Sxy, u64& Syy,
    u64& Sqx, u64& Sqy, u64& S1, u64& S2, u64& S3, u64& S4,
    unsigned saddr, u64 nvx2, u64 nvy2, u64 eps2)
{
    asm("{\n\t"
        ".reg .b64 kx2, ky2, qx2, qy2, dx, dy, w, wdx, wdy;\n\t"
        ".reg .f32 lo, hi;\n\t"
        "ld.shared.v2.b64 {kx2, ky2}, [%12];\n\t"
        "ld.shared.v2.b64 {qx2, qy2}, [%12+16];\n\t"
        "add.rn.f32x2 dx, kx2, %13;\n\t"
        "add.rn.f32x2 dy, ky2, %14;\n\t"
        "fma.rn.f32x2 w, dy, dy, %15;\n\t"
        "fma.rn.f32x2 w, dx, dx, w;\n\t"
        "mov.b64 {lo, hi}, w;\n\t"
        "rcp.approx.f32 lo, lo;\n\t"
        "rcp.approx.f32 hi, hi;\n\t"
        "mov.b64 w, {lo, hi};\n\t"
        "mul.rn.f32x2 wdx, w, dx;\n\t"
        "mul.rn.f32x2 wdy, w, dy;\n\t"
        "add.rn.f32x2 %0, %0, w;\n\t"
        "add.rn.f32x2 %1, %1, wdx;\n\t"
        "add.rn.f32x2 %2, %2, wdy;\n\t"
        "fma.rn.f32x2 %3, wdx, dx, %3;\n\t"
        "fma.rn.f32x2 %4, wdx, dy, %4;\n\t"
        "fma.rn.f32x2 %5, wdy, dy, %5;\n\t"
        "fma.rn.f32x2 %6, w, qx2, %6;\n\t"
        "fma.rn.f32x2 %7, w, qy2, %7;\n\t"
        "fma.rn.f32x2 %8, wdx, qx2, %8;\n\t"
        "fma.rn.f32x2 %9, wdy, qx2, %9;\n\t"
        "fma.rn.f32x2 %10, wdx, qy2, %10;\n\t"
        "fma.rn.f32x2 %11, wdy, qy2, %11;\n\t"
        "}"
        : "+l"(sw), "+l"(Sx), "+l"(Sy), "+l"(Sxx), "+l"(Sxy), "+l"(Syy),
          "+l"(Sqx), "+l"(Sqy), "+l"(S1), "+l"(S2), "+l"(S3), "+l"(S4)
        : "r"(saddr), "l"(nvx2), "l"(nvy2), "l"(eps2));
}

// Scalar epilogue: closed-form 2x2 solve from raw weighted moments.
//  m = Sigma w~ (pf - v)  ->  p* = v + m, u = v - p* = -m
__device__ __forceinline__ void mls_finish(
    float sw, float sx, float sy,
    float sxx, float sxy, float syy,
    float sqx, float sqy,
    float sdxqx, float sdyqx, float sdxqy, float sdyqy,
    float* __restrict__ ob, int pix)
{
    const float isw = frcp(sw);
    const float mx  = sx * isw,  my  = sy * isw;
    const float a11 = fmaf(sxx, isw, -(mx * mx));
    const float a12 = fmaf(sxy, isw, -(mx * my));
    const float a22 = fmaf(syy, isw, -(my * my));
    const float qsx = sqx * isw, qsy = sqy * isw;
    const float bxx = fmaf(sdxqx, isw, -(mx * qsx));
    const float bxy = fmaf(sdyqx, isw, -(my * qsx));
    const float byx = fmaf(sdxqy, isw, -(mx * qsy));
    const float byy = fmaf(sdyqy, isw, -(my * qsy));

    const float det  = fmaf(a11, a22, -(a12 * a12));
    const float idet = frcp(det);
    const float ux = -mx, uy = -my;
    const float rx = (ux * a22 - uy * a12) * idet;
    const float ry = (uy * a11 - ux * a12) * idet;

    float tx = fmaf(rx, bxx, fmaf(ry, bxy, qsx));
    float ty = fmaf(rx, byx, fmaf(ry, byy, qsy));

    // out-of-range pixels are ZEROED (not clipped)
    if (!(tx >= 0.f) || tx > (float)(GSZ - 1)) tx = 0.f;
    if (!(ty >= 0.f) || ty > (float)(GSZ - 1)) ty = 0.f;

    ob[pix]             = tx;   // channel 0 (x)
    ob[GSZ * GSZ + pix] = ty;   // channel 1 (y)
}

// 128 threads per CTA, each handles 2 pixels (pix, pix+128): same column,
// rows 4 apart. grid = (4, B): blockIdx.x selects an 8-row band.
__global__ __launch_bounds__(128)
void mls_warp_kernel(const float* __restrict__ sp,
                     const float* __restrict__ dp,
                     float* __restrict__ out)
{
    // Per control: 4 pre-duplicated f32x2 words: (kx,kx)(ky,ky)(qx,qx)(qy,qy)
    __shared__ __align__(32) u64 cs[NCTRL * 4];

    const int b    = blockIdx.y;
    const int band = blockIdx.x;     // 8-row band of the 32x32 grid
    const int tid  = threadIdx.x;

    if (tid < NCTRL) {
        const float* spb = sp + (size_t)b * (NCTRL * 2) + tid * 2;
        const float* dpb = dp + (size_t)b * (NCTRL * 2) + tid * 2;
        // coord swap + int16 truncation, exactly as the reference
        float kx = (float)(short)dpb[1];
        float ky = (float)(short)dpb[0];
        float qx = (float)(short)spb[1];
        float qy = (float)(short)spb[0];
        cs[tid * 4 + 0] = f2pack(kx, kx);
        cs[tid * 4 + 1] = f2pack(ky, ky);
        cs[tid * 4 + 2] = f2pack(qx, qx);
        cs[tid * 4 + 3] = f2pack(qy, qy);
    }
    __syncthreads();

    const int pixA = band * 256 + tid;         // pixB = pixA + 128
    const float vx  = (float)(tid & 31);
    const float vyA = (float)(band * 8 + (tid >> 5));
    const float vyB = vyA + 4.0f;

    const u64 nvx2 = f2pack(-vx, -vx);
    const u64 nvy2 = f2pack(-vyA, -vyB);
    const u64 eps2 = f2pack(MLS_EPS, MLS_EPS);

    u64 sw = 0, Sx = 0, Sy = 0;
    u64 Sxx = 0, Sxy = 0, Syy = 0;
    u64 Sqx = 0, Sqy = 0;
    u64 Sdxqx = 0, Sdyqx = 0, Sdxqy = 0, Sdyqy = 0;

    unsigned sbase = (unsigned)__cvta_generic_to_shared(cs);
#pragma unroll 4
    for (int c = 0; c < NCTRL; ++c) {
        mls_body(sw, Sx, Sy, Sxx, Sxy, Syy, Sqx, Sqy,
                 Sdxqx, Sdyqx, Sdxqy, Sdyqy,
                 sbase + (unsigned)c * 32u, nvx2, nvy2, eps2);
    }

    float* ob = out + (size_t)b * (2 * GSZ * GSZ);

    float swl, swh, sxl, sxh, syl, syh;
    float sxxl, sxxh, sxyl, sxyh, syyl, syyh;
    float sqxl, sqxh, sqyl, sqyh;
    float s1l, s1h, s2l, s2h, s3l, s3h, s4l, s4h;
    f2unpack(sw, swl, swh);    f2unpack(Sx, sxl, sxh);    f2unpack(Sy, syl, syh);
    f2unpack(Sxx, sxxl, sxxh); f2unpack(Sxy, sxyl, sxyh); f2unpack(Syy, syyl, syyh);
    f2unpack(Sqx, sqxl, sqxh); f2unpack(Sqy, sqyl, sqyh);
    f2unpack(Sdxqx, s1l, s1h); f2unpack(Sdyqx, s2l, s2h);
    f2unpack(Sdxqy, s3l, s3h); f2unpack(Sdyqy, s4l, s4h);

    mls_finish(swl, sxl, syl, sxxl, sxyl, syyl, sqxl, sqyl, s1l, s2l, s3l, s4l, ob, pixA);
    mls_finish(swh, sxh, syh, sxxh, sxyh, syyh, sqxh, sqyh, s1h, s2h, s3h, s4h, ob, pixA + 128);
}

extern "C" void kernel_launch(void* const* d_in, const int* in_sizes, int n_in,
                              void* d_out, int out_size)
{
    const float* sp = (const float*)d_in[0];   // (B, 68, 2)
    const float* dp = (const float*)d_in[1];   // (B, 68, 2)
    float* out = (float*)d_out;                // (B, 2, 32, 32)

    int B = in_sizes[0] / (NCTRL * 2);         // 512 for this problem
    dim3 grid(4, B);
    mls_warp_kernel<<<grid, 128>>>(sp, dp, out);
}

// round 13
// speedup vs baseline: 1.0440x; 1.0138x over previous
#include <cuda_runtime.h>
#include <cuda_bf16.h>

#define GSZ   32
#define NCTRL 68
#define MLS_EPS 1e-8f

typedef unsigned long long u64;

__device__ __forceinline__ u64 f2pack(float lo, float hi) {
    u64 r; asm("mov.b64 %0,{%1,%2};" : "=l"(r) : "f"(lo), "f"(hi)); return r;
}
__device__ __forceinline__ void f2unpack(u64 v, float& lo, float& hi) {
    asm("mov.b64 {%0,%1},%2;" : "=f"(lo), "=f"(hi) : "l"(v));
}
__device__ __forceinline__ float frcp(float x) {
    float r; asm("rcp.approx.f32 %0,%1;" : "=f"(r) : "f"(x)); return r;
}

// Per-control update for FOUR pixels (two f32x2 lane-sets A and B) in one asm
// block. All four pixels share the same column, so dx is computed once and the
// control words are loaded once. Two independent dependency chains (A and B)
// double per-thread ILP to cover LDS/MUFU latency and the FFMA2 bank-rt.
__device__ __forceinline__ void mls_body4(
    u64& swA, u64& SxA, u64& SyA, u64& SxxA, u64& SxyA, u64& SyyA,
    u64& SqxA, u64& SqyA, u64& S1A, u64& S2A, u64& S3A, u64& S4A,
    u64& swB, u64& SxB, u64& SyB, u64& SxxB, u64& SxyB, u64& SyyB,
    u64& SqxB, u64& SqyB, u64& S1B, u64& S2B, u64& S3B, u64& S4B,
    unsigned saddr, u64 nvx2, u64 nvyA2, u64 nvyB2, u64 eps2)
{
    asm("{\n\t"
        ".reg .b64 kx2, ky2, qx2, qy2, dx, dyA, dyB, wA, wB;\n\t"
        ".reg .b64 wdxA, wdyA, wdxB, wdyB;\n\t"
        ".reg .f32 lo, hi, lo2, hi2;\n\t"
        "ld.shared.v2.b64 {kx2, ky2}, [%24];\n\t"
        "ld.shared.v2.b64 {qx2, qy2}, [%24+16];\n\t"
        "add.rn.f32x2 dx, kx2, %25;\n\t"
        "add.rn.f32x2 dyA, ky2, %26;\n\t"
        "add.rn.f32x2 dyB, ky2, %27;\n\t"
        "fma.rn.f32x2 wA, dyA, dyA, %28;\n\t"
        "fma.rn.f32x2 wB, dyB, dyB, %28;\n\t"
        "fma.rn.f32x2 wA, dx, dx, wA;\n\t"
        "fma.rn.f32x2 wB, dx, dx, wB;\n\t"
        "mov.b64 {lo, hi}, wA;\n\t"
        "mov.b64 {lo2, hi2}, wB;\n\t"
        "rcp.approx.f32 lo, lo;\n\t"
        "rcp.approx.f32 hi, hi;\n\t"
        "rcp.approx.f32 lo2, lo2;\n\t"
        "rcp.approx.f32 hi2, hi2;\n\t"
        "mov.b64 wA, {lo, hi};\n\t"
        "mov.b64 wB, {lo2, hi2};\n\t"
        "mul.rn.f32x2 wdxA, wA, dx;\n\t"
        "mul.rn.f32x2 wdyA, wA, dyA;\n\t"
        "mul.rn.f32x2 wdxB, wB, dx;\n\t"
        "mul.rn.f32x2 wdyB, wB, dyB;\n\t"
        // set A accumulators
        "add.rn.f32x2 %0, %0, wA;\n\t"
        "add.rn.f32x2 %1, %1, wdxA;\n\t"
        "add.rn.f32x2 %2, %2, wdyA;\n\t"
        "fma.rn.f32x2 %3, wdxA, dx, %3;\n\t"
        "fma.rn.f32x2 %4, wdxA, dyA, %4;\n\t"
        "fma.rn.f32x2 %5, wdyA, dyA, %5;\n\t"
        "fma.rn.f32x2 %6, wA, qx2, %6;\n\t"
        "fma.rn.f32x2 %7, wA, qy2, %7;\n\t"
        "fma.rn.f32x2 %8, wdxA, qx2, %8;\n\t"
        "fma.rn.f32x2 %9, wdyA, qx2, %9;\n\t"
        "fma.rn.f32x2 %10, wdxA, qy2, %10;\n\t"
        "fma.rn.f32x2 %11, wdyA, qy2, %11;\n\t"
        // set B accumulators
        "add.rn.f32x2 %12, %12, wB;\n\t"
        "add.rn.f32x2 %13, %13, wdxB;\n\t"
        "add.rn.f32x2 %14, %14, wdyB;\n\t"
        "fma.rn.f32x2 %15, wdxB, dx, %15;\n\t"
        "fma.rn.f32x2 %16, wdxB, dyB, %16;\n\t"
        "fma.rn.f32x2 %17, wdyB, dyB, %17;\n\t"
        "fma.rn.f32x2 %18, wB, qx2, %18;\n\t"
        "fma.rn.f32x2 %19, wB, qy2, %19;\n\t"
        "fma.rn.f32x2 %20, wdxB, qx2, %20;\n\t"
        "fma.rn.f32x2 %21, wdyB, qx2, %21;\n\t"
        "fma.rn.f32x2 %22, wdxB, qy2, %22;\n\t"
        "fma.rn.f32x2 %23, wdyB, qy2, %23;\n\t"
        "}"
        : "+l"(swA), "+l"(SxA), "+l"(SyA), "+l"(SxxA), "+l"(SxyA), "+l"(SyyA),
          "+l"(SqxA), "+l"(SqyA), "+l"(S1A), "+l"(S2A), "+l"(S3A), "+l"(S4A),
          "+l"(swB), "+l"(SxB), "+l"(SyB), "+l"(SxxB), "+l"(SxyB), "+l"(SyyB),
          "+l"(SqxB), "+l"(SqyB), "+l"(S1B), "+l"(S2B), "+l"(S3B), "+l"(S4B)
        : "r"(saddr), "l"(nvx2), "l"(nvyA2), "l"(nvyB2), "l"(eps2));
}

// Scalar epilogue: closed-form 2x2 solve from raw weighted moments.
//  m = Sigma w~ (pf - v)  ->  p* = v + m, u = v - p* = -m
__device__ __forceinline__ void mls_finish(
    float sw, float sx, float sy,
    float sxx, float sxy, float syy,
    float sqx, float sqy,
    float sdxqx, float sdyqx, float sdxqy, float sdyqy,
    float* __restrict__ ob, int pix)
{
    const float isw = frcp(sw);
    const float mx  = sx * isw,  my  = sy * isw;
    const float a11 = fmaf(sxx, isw, -(mx * mx));
    const float a12 = fmaf(sxy, isw, -(mx * my));
    const float a22 = fmaf(syy, isw, -(my * my));
    const float qsx = sqx * isw, qsy = sqy * isw;
    const float bxx = fmaf(sdxqx, isw, -(mx * qsx));
    const float bxy = fmaf(sdyqx, isw, -(my * qsx));
    const float byx = fmaf(sdxqy, isw, -(mx * qsy));
    const float byy = fmaf(sdyqy, isw, -(my * qsy));

    const float det  = fmaf(a11, a22, -(a12 * a12));
    const float idet = frcp(det);
    const float ux = -mx, uy = -my;
    const float rx = (ux * a22 - uy * a12) * idet;
    const float ry = (uy * a11 - ux * a12) * idet;

    float tx = fmaf(rx, bxx, fmaf(ry, bxy, qsx));
    float ty = fmaf(rx, byx, fmaf(ry, byy, qsy));

    // out-of-range pixels are ZEROED (not clipped)
    if (!(tx >= 0.f) || tx > (float)(GSZ - 1)) tx = 0.f;
    if (!(ty >= 0.f) || ty > (float)(GSZ - 1)) ty = 0.f;

    ob[pix]             = tx;   // channel 0 (x)
    ob[GSZ * GSZ + pix] = ty;   // channel 1 (y)
}

// 128 threads per CTA, each handles 4 pixels in one column: rows r0, r0+4,
// r0+8, r0+12 of a 16-row band. grid = (2, B).
__global__ __launch_bounds__(128)
void mls_warp_kernel(const float* __restrict__ sp,
                     const float* __restrict__ dp,
                     float* __restrict__ out)
{
    // Per control: 4 pre-duplicated f32x2 words: (kx,kx)(ky,ky)(qx,qx)(qy,qy)
    __shared__ __align__(32) u64 cs[NCTRL * 4];

    const int b    = blockIdx.y;
    const int band = blockIdx.x;     // 16-row band of the 32x32 grid
    const int tid  = threadIdx.x;

    if (tid < NCTRL) {
        const float* spb = sp + (size_t)b * (NCTRL * 2) + tid * 2;
        const float* dpb = dp + (size_t)b * (NCTRL * 2) + tid * 2;
        // coord swap + int16 truncation, exactly as the reference
        float kx = (float)(short)dpb[1];
        float ky = (float)(short)dpb[0];
        float qx = (float)(short)spb[1];
        float qy = (float)(short)spb[0];
        cs[tid * 4 + 0] = f2pack(kx, kx);
        cs[tid * 4 + 1] = f2pack(ky, ky);
        cs[tid * 4 + 2] = f2pack(qx, qx);
        cs[tid * 4 + 3] = f2pack(qy, qy);
    }
    __syncthreads();

    const int pix0 = band * 512 + tid;         // pixels at pix0 + {0,128,256,384}
    const float vx = (float)(tid & 31);
    const float r0 = (float)(band * 16 + (tid >> 5));

    const u64 nvx2  = f2pack(-vx, -vx);
    const u64 nvyA2 = f2pack(-r0,          -(r0 + 4.0f));   // set A: rows r0, r0+4
    const u64 nvyB2 = f2pack(-(r0 + 8.0f), -(r0 + 12.0f));  // set B: rows r0+8, r0+12
    const u64 eps2  = f2pack(MLS_EPS, MLS_EPS);

    u64 swA = 0, SxA = 0, SyA = 0, SxxA = 0, SxyA = 0, SyyA = 0;
    u64 SqxA = 0, SqyA = 0, S1A = 0, S2A = 0, S3A = 0, S4A = 0;
    u64 swB = 0, SxB = 0, SyB = 0, SxxB = 0, SxyB = 0, SyyB = 0;
    u64 SqxB = 0, SqyB = 0, S1B = 0, S2B = 0, S3B = 0, S4B = 0;

    unsigned sbase = (unsigned)__cvta_generic_to_shared(cs);
#pragma unroll 2
    for (int c = 0; c < NCTRL; ++c) {
        mls_body4(swA, SxA, SyA, SxxA, SxyA, SyyA, SqxA, SqyA, S1A, S2A, S3A, S4A,
                  swB, SxB, SyB, SxxB, SxyB, SyyB, SqxB, SqyB, S1B, S2B, S3B, S4B,
                  sbase + (unsigned)c * 32u, nvx2, nvyA2, nvyB2, eps2);
    }

    float* ob = out + (size_t)b * (2 * GSZ * GSZ);

    {   // set A -> pixels pix0, pix0+128
        float swl, swh, sxl, sxh, syl, syh, sxxl, sxxh, sxyl, sxyh, syyl, syyh;
        float sqxl, sqxh, sqyl, sqyh, s1l, s1h, s2l, s2h, s3l, s3h, s4l, s4h;
        f2unpack(swA, swl, swh);   f2unpack(SxA, sxl, sxh);   f2unpack(SyA, syl, syh);
        f2unpack(SxxA, sxxl, sxxh); f2unpack(SxyA, sxyl, sxyh); f2unpack(SyyA, syyl, syyh);
        f2unpack(SqxA, sqxl, sqxh); f2unpack(SqyA, sqyl, sqyh);
        f2unpack(S1A, s1l, s1h); f2unpack(S2A, s2l, s2h);
        f2unpack(S3A, s3l, s3h); f2unpack(S4A, s4l, s4h);
        mls_finish(swl, sxl, syl, sxxl, sxyl, syyl, sqxl, sqyl, s1l, s2l, s3l, s4l, ob, pix0);
        mls_finish(swh, sxh, syh, sxxh, sxyh, syyh, sqxh, sqyh, s1h, s2h, s3h, s4h, ob, pix0 + 128);
    }
    {   // set B -> pixels pix0+256, pix0+384
        float swl, swh, sxl, sxh, syl, syh, sxxl, sxxh, sxyl, sxyh, syyl, syyh;
        float sqxl, sqxh, sqyl, sqyh, s1l, s1h, s2l, s2h, s3l, s3h, s4l, s4h;
        f2unpack(swB, swl, swh);   f2unpack(SxB, sxl, sxh);   f2unpack(SyB, syl, syh);
        f2unpack(SxxB, sxxl, sxxh); f2unpack(SxyB, sxyl, sxyh); f2unpack(SyyB, syyl, syyh);
        f2unpack(SqxB, sqxl, sqxh); f2unpack(SqyB, sqyl, sqyh);
        f2unpack(S1B, s1l, s1h); f2unpack(S2B, s2l, s2h);
        f2unpack(S3B, s3l, s3h); f2unpack(S4B, s4l, s4h);
        mls_finish(swl, sxl, syl, sxxl, sxyl, syyl, sqxl, sqyl, s1l, s2l, s3l, s4l, ob, pix0 + 256);
        mls_finish(swh, sxh, syh, sxxh, sxyh, syyh, sqxh, sqyh, s1h, s2h, s3h, s4h, ob, pix0 + 384);
    }
}

extern "C" void kernel_launch(void* const* d_in, const int* in_sizes, int n_in,
                              void* d_out, int out_size)
{
    const float* sp = (const float*)d_in[0];   // (B, 68, 2)
    const float* dp = (const float*)d_in[1];   // (B, 68, 2)
    float* out = (float*)d_out;                // (B, 2, 32, 32)

    int B = in_sizes[0] / (NCTRL * 2);         // 512 for this problem
    dim3 grid(2, B);
    mls_warp_kernel<<<grid, 128>>>(sp, dp, out);
}